// round 16
// baseline (speedup 1.0000x reference)
#include <cuda_runtime.h>
#include <cuda_bf16.h>
#include <stdint.h>

#define NNODES 100000
#define NEDGES 1600000
#define FDIM   128
#define LAT    64
#define CAP    64            // ELL slots per node; P(in-deg >= 64) ~ e^-40

// ---------------- scratch ----------------------------------------------------
__device__ __nv_bfloat16 g_t[(size_t)NNODES * FDIM];  // t = x @ W1, bf16 (25.6 MB)
__device__ unsigned long long g_pack[NNODES];   // [63:40] cnt, [39:0] sum(w) Q24
__device__ float g_dinv[NNODES];
__device__ float g_c[NNODES];                   // column sums of Anorm
__device__ int   g_cnt[NNODES];                 // in-degree counts (clamped to CAP)
__device__ int2  g_ell[(size_t)NNODES * CAP];   // ELL: {src, w/norm bits} (51.2 MB)
__device__ float g_v[FDIM];                     // v = sum_i c_i * h1[i]

__device__ __forceinline__ void red_add_v4(float* p, float4 m) {
    asm volatile("red.global.add.v4.f32 [%0], {%1,%2,%3,%4};"
                 :: "l"(p), "f"(m.x), "f"(m.y), "f"(m.z), "f"(m.w) : "memory");
}

__device__ __forceinline__ unsigned pack_bf2(float lo, float hi) {
    __nv_bfloat162 p = __float22bfloat162_rn(make_float2(lo, hi));
    return *reinterpret_cast<unsigned*>(&p);
}

// 8 bf16 (uint4) -> 8 floats
__device__ __forceinline__ void bf8_to_f8(uint4 u, float* f) {
    __nv_bfloat162 p0 = *reinterpret_cast<__nv_bfloat162*>(&u.x);
    __nv_bfloat162 p1 = *reinterpret_cast<__nv_bfloat162*>(&u.y);
    __nv_bfloat162 p2 = *reinterpret_cast<__nv_bfloat162*>(&u.z);
    __nv_bfloat162 p3 = *reinterpret_cast<__nv_bfloat162*>(&u.w);
    float2 a = __bfloat1622float2(p0);
    float2 b = __bfloat1622float2(p1);
    float2 c = __bfloat1622float2(p2);
    float2 d = __bfloat1622float2(p3);
    f[0] = a.x; f[1] = a.y; f[2] = b.x; f[3] = b.y;
    f[4] = c.x; f[5] = c.y; f[6] = d.x; f[7] = d.y;
}

// ---------------- kernels -----------------------------------------------------

__global__ void k_init(int n) {
    int i = blockIdx.x * blockDim.x + threadIdx.x;
    if (i < n) g_pack[i] = 0ull;
    if (i < FDIM) g_v[i] = 0.f;
}

// ONE edge pass: a single packed 64-bit atomic yields this edge's slot
// (old>>40) AND accumulates the weighted degree (Q24, low 40 bits).
__global__ void k_build(const int* __restrict__ src, const int* __restrict__ dst,
                        const float* __restrict__ w, int e) {
    int i = blockIdx.x * blockDim.x + threadIdx.x;
    if (i < e) {
        int d = dst[i];
        float wi = w[i];
        unsigned long long pk = (1ull << 40)
            | (unsigned long long)(unsigned)(wi * 16777216.0f);
        unsigned long long old = atomicAdd(&g_pack[d], pk);
        int slot = (int)(old >> 40);
        if (slot < CAP)
            g_ell[((size_t)d << 6) + slot] = make_int2(src[i], __float_as_int(wi));
    }
}

// node pass: decode pack -> dinv/cnt, c = self contribution; reset pack
__global__ void k_decode(int n) {
    int i = blockIdx.x * blockDim.x + threadIdx.x;
    if (i < n) {
        unsigned long long pk = g_pack[i];
        g_pack[i] = 0ull;   // ready for next replay
        int cnt = (int)(pk >> 40);
        if (cnt > CAP) cnt = CAP;
        float degw = 1.0f + (float)(pk & 0xFFFFFFFFFFull) * (1.0f / 16777216.0f);
        float di = rsqrtf(degw);
        g_dinv[i] = di;
        g_c[i] = di * di;     // self-loop column contribution
        g_cnt[i] = cnt;
    }
}

// slot pass: finish per-edge norm in place, accumulate column sums c[src]
__global__ void k_cacc(int n) {
    int idx = blockIdx.x * blockDim.x + threadIdx.x;
    int i = idx >> 6;         // node
    int k = idx & 63;         // slot
    if (i < n && k < __ldg(&g_cnt[i])) {
        int2 sl = g_ell[idx];
        float nm = __ldg(&g_dinv[sl.x]) * __int_as_float(sl.y) * __ldg(&g_dinv[i]);
        g_ell[idx].y = __float_as_int(nm);
        atomicAdd(&g_c[sl.x], nm);
    }
}

// ---------------- tensor-core GEMM: t = bf16(x) @ bf16(W1), fp32 accum -------
#define SROW 136
__global__ __launch_bounds__(256) void k_gemm_tc(const float* __restrict__ x,
                                                 const float* __restrict__ W,
                                                 int n) {
    extern __shared__ __nv_bfloat16 smem[];
    __nv_bfloat16 (*sA)[SROW] = (__nv_bfloat16(*)[SROW])smem;                 // x rows
    __nv_bfloat16 (*sB)[SROW] = (__nv_bfloat16(*)[SROW])(smem + 128 * SROW);  // W^T
    const int tid = threadIdx.x;
    const int br  = blockIdx.x * 128;

    for (int idx = tid; idx < FDIM * FDIM; idx += 256) {
        int k = idx >> 7, c = idx & 127;
        sB[c][k] = __float2bfloat16(W[idx]);
    }
    for (int idx = tid; idx < 128 * 32; idx += 256) {
        int r = idx >> 5, q = idx & 31;
        int gr = br + r; if (gr >= n) gr = n - 1;
        float4 v = __ldg((const float4*)(x + (size_t)gr * FDIM) + q);
        __nv_bfloat16* p = &sA[r][q * 4];
        p[0] = __float2bfloat16(v.x);
        p[1] = __float2bfloat16(v.y);
        p[2] = __float2bfloat16(v.z);
        p[3] = __float2bfloat16(v.w);
    }
    __syncthreads();

    const int wid  = tid >> 5, lane = tid & 31;
    const int g    = lane >> 2;
    const int tg   = lane & 3;
    const int row0 = wid * 16;

    float c[16][4];
#pragma unroll
    for (int t = 0; t < 16; t++)
#pragma unroll
        for (int q = 0; q < 4; q++) c[t][q] = 0.f;

#pragma unroll
    for (int k0 = 0; k0 < FDIM; k0 += 16) {
        unsigned a0 = *(const unsigned*)&sA[row0 + g][k0 + tg * 2];
        unsigned a1 = *(const unsigned*)&sA[row0 + g + 8][k0 + tg * 2];
        unsigned a2 = *(const unsigned*)&sA[row0 + g][k0 + tg * 2 + 8];
        unsigned a3 = *(const unsigned*)&sA[row0 + g + 8][k0 + tg * 2 + 8];
#pragma unroll
        for (int t = 0; t < 16; t++) {
            unsigned b0 = *(const unsigned*)&sB[t * 8 + g][k0 + tg * 2];
            unsigned b1 = *(const unsigned*)&sB[t * 8 + g][k0 + tg * 2 + 8];
            asm volatile(
                "mma.sync.aligned.m16n8k16.row.col.f32.bf16.bf16.f32 "
                "{%0,%1,%2,%3}, {%4,%5,%6,%7}, {%8,%9}, {%0,%1,%2,%3};"
                : "+f"(c[t][0]), "+f"(c[t][1]), "+f"(c[t][2]), "+f"(c[t][3])
                : "r"(a0), "r"(a1), "r"(a2), "r"(a3), "r"(b0), "r"(b1));
        }
    }

    int r0 = br + row0 + g;
    int r1 = r0 + 8;
#pragma unroll
    for (int t = 0; t < 16; t++) {
        int col = t * 8 + tg * 2;
        if (r0 < n) *(unsigned*)(g_t + (size_t)r0 * FDIM + col) = pack_bf2(c[t][0], c[t][1]);
        if (r1 < n) *(unsigned*)(g_t + (size_t)r1 * FDIM + col) = pack_bf2(c[t][2], c[t][3]);
    }
}

// fused gather + finalize. Half-warp per edge (16 lanes x 16B = 256B row),
// 4 edges per half-warp batch with next-batch ELL-entry prefetch.
// ELL: node i's edges at [i*64, i*64+cnt) — no rowptr load.
__global__ __launch_bounds__(256) void k_gather(const float* __restrict__ b1, int n) {
    const int lane = threadIdx.x & 31;
    const int half = lane >> 4;
    const int hl   = lane & 15;
    const int wid  = threadIdx.x >> 5;
    const int gw   = blockIdx.x * 8 + wid;
    const int nw   = gridDim.x * 8;
    const uint4* trows = (const uint4*)g_t;   // 16 uint4 per row

    float b[8];
    {
        float4 b0 = __ldg((const float4*)b1 + hl * 2);
        float4 b1v = __ldg((const float4*)b1 + hl * 2 + 1);
        b[0] = b0.x; b[1] = b0.y; b[2] = b0.z; b[3] = b0.w;
        b[4] = b1v.x; b[5] = b1v.y; b[6] = b1v.z; b[7] = b1v.w;
    }
    float vacc[8];
#pragma unroll
    for (int k = 0; k < 8; k++) vacc[k] = 0.f;

    for (int i = gw; i < n; i += nw) {
        int beg = i << 6;
        int end = beg + __ldg(&g_cnt[i]);
        float acc[8];
        {
            float di = __ldg(g_dinv + i);
            float selfw = half ? 0.f : di * di;
            float f[8];
            bf8_to_f8(__ldg(trows + ((size_t)i << 4) + hl), f);
#pragma unroll
            for (int k = 0; k < 8; k++) acc[k] = selfw * f[k];
        }
        int j = beg + half;
        if (j + 6 < end) {
            int2 e0 = __ldg(g_ell + j);
            int2 e1 = __ldg(g_ell + j + 2);
            int2 e2 = __ldg(g_ell + j + 4);
            int2 e3 = __ldg(g_ell + j + 6);
            while (true) {
                int jn = j + 8;
                bool more = (jn + 6 < end);
                int2 p0, p1, p2, p3;
                if (more) {
                    p0 = __ldg(g_ell + jn);
                    p1 = __ldg(g_ell + jn + 2);
                    p2 = __ldg(g_ell + jn + 4);
                    p3 = __ldg(g_ell + jn + 6);
                }
                uint4 u0 = __ldg(trows + ((size_t)e0.x << 4) + hl);
                uint4 u1 = __ldg(trows + ((size_t)e1.x << 4) + hl);
                uint4 u2 = __ldg(trows + ((size_t)e2.x << 4) + hl);
                uint4 u3 = __ldg(trows + ((size_t)e3.x << 4) + hl);
                float f0[8], f1[8], f2[8], f3[8];
                bf8_to_f8(u0, f0);
                bf8_to_f8(u1, f1);
                bf8_to_f8(u2, f2);
                bf8_to_f8(u3, f3);
                float n0 = __int_as_float(e0.y);
                float n1 = __int_as_float(e1.y);
                float n2 = __int_as_float(e2.y);
                float n3 = __int_as_float(e3.y);
#pragma unroll
                for (int k = 0; k < 8; k++) acc[k] = fmaf(n0, f0[k], acc[k]);
#pragma unroll
                for (int k = 0; k < 8; k++) acc[k] = fmaf(n1, f1[k], acc[k]);
#pragma unroll
                for (int k = 0; k < 8; k++) acc[k] = fmaf(n2, f2[k], acc[k]);
#pragma unroll
                for (int k = 0; k < 8; k++) acc[k] = fmaf(n3, f3[k], acc[k]);
                j = jn;
                if (!more) break;
                e0 = p0; e1 = p1; e2 = p2; e3 = p3;
            }
        }
        for (; j < end; j += 2) {
            int2 e0 = __ldg(g_ell + j);
            float f0[8];
            bf8_to_f8(__ldg(trows + ((size_t)e0.x << 4) + hl), f0);
            float n0 = __int_as_float(e0.y);
#pragma unroll
            for (int k = 0; k < 8; k++) acc[k] = fmaf(n0, f0[k], acc[k]);
        }
#pragma unroll
        for (int k = 0; k < 8; k++) acc[k] += __shfl_xor_sync(~0u, acc[k], 16);
        if (!half) {
            float ci = __ldg(g_c + i);
#pragma unroll
            for (int k = 0; k < 8; k++) {
                float h = fmaxf(acc[k] + b[k], 0.f);
                vacc[k] = fmaf(ci, h, vacc[k]);
            }
        }
    }

    __shared__ float sv[FDIM];
    if (threadIdx.x < FDIM) sv[threadIdx.x] = 0.f;
    __syncthreads();
    if (!half) {
#pragma unroll
        for (int k = 0; k < 8; k++) atomicAdd(&sv[hl * 8 + k], vacc[k]);
    }
    __syncthreads();
    if (threadIdx.x < 32) {
        float4 p = *(const float4*)&sv[threadIdx.x * 4];
        red_add_v4(g_v + threadIdx.x * 4, p);
    }
}

// head
__global__ void k_head(const float* __restrict__ W2, const float* __restrict__ b2,
                       const float* __restrict__ Wmu, const float* __restrict__ bmu,
                       const float* __restrict__ Wlv, const float* __restrict__ blv,
                       float* __restrict__ out, float invn) {
    __shared__ float vs[FDIM];
    __shared__ float gs[FDIM];
    int j = threadIdx.x;
    vs[j] = g_v[j];
    __syncthreads();
    float s = 0.f;
#pragma unroll 8
    for (int k = 0; k < FDIM; k++) s = fmaf(vs[k], W2[(size_t)k * FDIM + j], s);
    gs[j] = s * invn + b2[j];
    __syncthreads();
    if (j < LAT) {
        float m = bmu[j];
#pragma unroll 8
        for (int k = 0; k < FDIM; k++) m = fmaf(gs[k], Wmu[(size_t)k * LAT + j], m);
        out[j] = m;
    } else {
        int l = j - LAT;
        float m = blv[l];
#pragma unroll 8
        for (int k = 0; k < FDIM; k++) m = fmaf(gs[k], Wlv[(size_t)k * LAT + l], m);
        out[LAT + l] = m;
    }
}

// ---------------- launch -------------------------------------------------------
extern "C" void kernel_launch(void* const* d_in, const int* in_sizes, int n_in,
                              void* d_out, int out_size) {
    const float* x   = (const float*)d_in[0];
    const int*   ei  = (const int*)d_in[1];
    const float* w   = (const float*)d_in[2];
    const float* W1  = (const float*)d_in[3];
    const float* b1  = (const float*)d_in[4];
    const float* W2  = (const float*)d_in[5];
    const float* b2  = (const float*)d_in[6];
    const float* Wmu = (const float*)d_in[7];
    const float* bmu = (const float*)d_in[8];
    const float* Wlv = (const float*)d_in[9];
    const float* blv = (const float*)d_in[10];
    float* out = (float*)d_out;

    const int n = in_sizes[0] / FDIM;
    const int e = in_sizes[2];
    const int* src = ei;
    const int* dst = ei + e;
    const int smem_gemm = 2 * 128 * SROW * (int)sizeof(__nv_bfloat16);  // 69,632 B

    static int s_attr_done = 0;
    if (!s_attr_done) {
        cudaFuncSetAttribute(k_gemm_tc, cudaFuncAttributeMaxDynamicSharedMemorySize, smem_gemm);
        s_attr_done = 1;
    }

    // Side stream for the independent GEMM (capture fork pattern, fork at t=0).
    cudaStream_t s2;
    cudaStreamCreate(&s2);
    cudaEvent_t ev_fork, ev_join;
    cudaEventCreateWithFlags(&ev_fork, cudaEventDisableTiming);
    cudaEventCreateWithFlags(&ev_join, cudaEventDisableTiming);

    cudaEventRecord(ev_fork, 0);
    cudaStreamWaitEvent(s2, ev_fork, 0);
    k_gemm_tc<<<(n + 127) / 128, 256, smem_gemm, s2>>>(x, W1, n);
    cudaEventRecord(ev_join, s2);

    // ELL-build chain (main stream), concurrent with GEMM.
    k_init<<<(n + 255) / 256, 256>>>(n);
    k_build<<<(e + 255) / 256, 256>>>(src, dst, w, e);
    k_decode<<<(n + 255) / 256, 256>>>(n);
    {
        long long slots = (long long)n * CAP;
        k_cacc<<<(int)((slots + 255) / 256), 256>>>(n);
    }

    cudaStreamWaitEvent(0, ev_join, 0);
    k_gather<<<1184, 256>>>(b1, n);
    k_head<<<1, FDIM>>>(W2, b2, Wmu, bmu, Wlv, blv, out, 1.0f / (float)n);
}

// round 17
// speedup vs baseline: 1.0967x; 1.0967x over previous
#include <cuda_runtime.h>
#include <cuda_bf16.h>
#include <stdint.h>

#define NNODES 100000
#define NEDGES 1600000
#define FDIM   128
#define LAT    64
#define SCAN_ELEMS 256
#define NBLK_SCAN ((NNODES + SCAN_ELEMS - 1) / SCAN_ELEMS)   // 391

// ---------------- scratch ----------------------------------------------------
__device__ __nv_bfloat16 g_t[(size_t)NNODES * FDIM];  // t = x @ W1, bf16 (25.6 MB)
__device__ unsigned long long g_pack[NNODES];   // [63:40] cnt, [39:0] sum(w) Q24
__device__ float g_dinv[NNODES];
__device__ float g_c[NNODES];                   // column sums of Anorm
__device__ int   g_cnt[NNODES];                 // in-degree counts
__device__ int   g_rowptr[NNODES];              // CSR cursor (post-fill = row end)
__device__ int   g_bsum[NBLK_SCAN + 32];        // scan partials
__device__ int2  g_csr[NEDGES];                 // packed {src, norm-as-bits}
__device__ float g_v[FDIM];                     // v = sum_i c_i * h1[i]

__device__ __forceinline__ void red_add_v4(float* p, float4 m) {
    asm volatile("red.global.add.v4.f32 [%0], {%1,%2,%3,%4};"
                 :: "l"(p), "f"(m.x), "f"(m.y), "f"(m.z), "f"(m.w) : "memory");
}

__device__ __forceinline__ void red_add_u64(unsigned long long* p, unsigned long long v) {
    asm volatile("red.global.add.u64 [%0], %1;" :: "l"(p), "l"(v) : "memory");
}

__device__ __forceinline__ void red_add_f32(float* p, float v) {
    asm volatile("red.global.add.f32 [%0], %1;" :: "l"(p), "f"(v) : "memory");
}

__device__ __forceinline__ unsigned pack_bf2(float lo, float hi) {
    __nv_bfloat162 p = __float22bfloat162_rn(make_float2(lo, hi));
    return *reinterpret_cast<unsigned*>(&p);
}

// 8 bf16 (uint4) -> 8 floats
__device__ __forceinline__ void bf8_to_f8(uint4 u, float* f) {
    __nv_bfloat162 p0 = *reinterpret_cast<__nv_bfloat162*>(&u.x);
    __nv_bfloat162 p1 = *reinterpret_cast<__nv_bfloat162*>(&u.y);
    __nv_bfloat162 p2 = *reinterpret_cast<__nv_bfloat162*>(&u.z);
    __nv_bfloat162 p3 = *reinterpret_cast<__nv_bfloat162*>(&u.w);
    float2 a = __bfloat1622float2(p0);
    float2 b = __bfloat1622float2(p1);
    float2 c = __bfloat1622float2(p2);
    float2 d = __bfloat1622float2(p3);
    f[0] = a.x; f[1] = a.y; f[2] = b.x; f[3] = b.y;
    f[4] = c.x; f[5] = c.y; f[6] = d.x; f[7] = d.y;
}

// ---------------- kernels -----------------------------------------------------

__global__ void k_init(int n) {
    int i = blockIdx.x * blockDim.x + threadIdx.x;
    if (i < n) g_pack[i] = 0ull;
    if (i < FDIM) g_v[i] = 0.f;
}

// one packed 64-bit REDG per edge; ONE edge per thread (atomic-latency-bound)
__global__ void k_hist(const int* __restrict__ dst, const float* __restrict__ w, int e) {
    int i = blockIdx.x * blockDim.x + threadIdx.x;
    if (i < e) {
        unsigned long long pk = (1ull << 40)
            | (unsigned long long)(unsigned)(w[i] * 16777216.0f);
        red_add_u64(&g_pack[dst[i]], pk);
    }
}

// decode pack -> cnt/dinv/c (+ zero pack), block scan of 256 elems (1/thread)
__global__ void k_scan1(int n) {
    __shared__ int warp_sums[8];
    int tid = threadIdx.x;
    int i = blockIdx.x * SCAN_ELEMS + tid;
    int cnt = 0;
    if (i < n) {
        unsigned long long pk = g_pack[i];
        g_pack[i] = 0ull;   // reset for next replay
        cnt = (int)(pk >> 40);
        float degw = 1.0f + (float)(pk & 0xFFFFFFFFFFull) * (1.0f / 16777216.0f);
        float di = rsqrtf(degw);
        g_dinv[i] = di;
        g_c[i] = di * di;
        g_cnt[i] = cnt;
    }
    int lane = tid & 31, wid = tid >> 5;
    int s = cnt;
#pragma unroll
    for (int o = 1; o < 32; o <<= 1) { int u = __shfl_up_sync(~0u, s, o); if (lane >= o) s += u; }
    if (lane == 31) warp_sums[wid] = s;
    __syncthreads();
    if (wid == 0) {
        int ws = (lane < 8) ? warp_sums[lane] : 0;
#pragma unroll
        for (int o = 1; o < 8; o <<= 1) { int u = __shfl_up_sync(~0u, ws, o); if (lane >= o) ws += u; }
        if (lane < 8) warp_sums[lane] = ws;
    }
    __syncthreads();
    int excl = s - cnt + (wid > 0 ? warp_sums[wid - 1] : 0);
    if (i < n) g_rowptr[i] = excl;
    if (tid == 255) g_bsum[blockIdx.x] = excl + cnt;
}

// scan 391 block partials with one 512-thread block
__global__ void k_scan2(int nb) {
    __shared__ int ws[16];
    int tid = threadIdx.x;
    int v = (tid < nb) ? g_bsum[tid] : 0;
    int lane = tid & 31, wid = tid >> 5;   // 16 warps
    int s = v;
#pragma unroll
    for (int o = 1; o < 32; o <<= 1) { int u = __shfl_up_sync(~0u, s, o); if (lane >= o) s += u; }
    if (lane == 31) ws[wid] = s;
    __syncthreads();
    if (wid == 0) {
        int t = (lane < 16) ? ws[lane] : 0;
#pragma unroll
        for (int o = 1; o < 16; o <<= 1) { int u = __shfl_up_sync(~0u, t, o); if (lane >= o) t += u; }
        if (lane < 16) ws[lane] = t;
    }
    __syncthreads();
    int add = (wid > 0) ? ws[wid - 1] : 0;
    if (tid < nb) g_bsum[tid] = s + add - v;   // exclusive
}

__global__ void k_scan3(int n) {
    int i = blockIdx.x * blockDim.x + threadIdx.x;
    if (i < n) g_rowptr[i] += g_bsum[i >> 8];   // SCAN_ELEMS = 256
}

// CSR fill: rowptr doubles as cursor (post-fill = row END); ONE edge per thread
__global__ void k_fill(const int* __restrict__ src, const int* __restrict__ dst,
                       const float* __restrict__ w, int e) {
    int i = blockIdx.x * blockDim.x + threadIdx.x;
    if (i < e) {
        int s = src[i], d = dst[i];
        float nm = g_dinv[s] * w[i] * g_dinv[d];
        int p = atomicAdd(&g_rowptr[d], 1);
        g_csr[p] = make_int2(s, __float_as_int(nm));
        red_add_f32(&g_c[s], nm);
    }
}

// ---------------- tensor-core GEMM: t = bf16(x) @ bf16(W1), fp32 accum -------
#define SROW 136
__global__ __launch_bounds__(256) void k_gemm_tc(const float* __restrict__ x,
                                                 const float* __restrict__ W,
                                                 int n) {
    extern __shared__ __nv_bfloat16 smem[];
    __nv_bfloat16 (*sA)[SROW] = (__nv_bfloat16(*)[SROW])smem;                 // x rows
    __nv_bfloat16 (*sB)[SROW] = (__nv_bfloat16(*)[SROW])(smem + 128 * SROW);  // W^T
    const int tid = threadIdx.x;
    const int br  = blockIdx.x * 128;

    for (int idx = tid; idx < FDIM * FDIM; idx += 256) {
        int k = idx >> 7, c = idx & 127;
        sB[c][k] = __float2bfloat16(W[idx]);
    }
    for (int idx = tid; idx < 128 * 32; idx += 256) {
        int r = idx >> 5, q = idx & 31;
        int gr = br + r; if (gr >= n) gr = n - 1;
        float4 v = __ldg((const float4*)(x + (size_t)gr * FDIM) + q);
        __nv_bfloat16* p = &sA[r][q * 4];
        p[0] = __float2bfloat16(v.x);
        p[1] = __float2bfloat16(v.y);
        p[2] = __float2bfloat16(v.z);
        p[3] = __float2bfloat16(v.w);
    }
    __syncthreads();

    const int wid  = tid >> 5, lane = tid & 31;
    const int g    = lane >> 2;
    const int tg   = lane & 3;
    const int row0 = wid * 16;

    float c[16][4];
#pragma unroll
    for (int t = 0; t < 16; t++)
#pragma unroll
        for (int q = 0; q < 4; q++) c[t][q] = 0.f;

#pragma unroll
    for (int k0 = 0; k0 < FDIM; k0 += 16) {
        unsigned a0 = *(const unsigned*)&sA[row0 + g][k0 + tg * 2];
        unsigned a1 = *(const unsigned*)&sA[row0 + g + 8][k0 + tg * 2];
        unsigned a2 = *(const unsigned*)&sA[row0 + g][k0 + tg * 2 + 8];
        unsigned a3 = *(const unsigned*)&sA[row0 + g + 8][k0 + tg * 2 + 8];
#pragma unroll
        for (int t = 0; t < 16; t++) {
            unsigned b0 = *(const unsigned*)&sB[t * 8 + g][k0 + tg * 2];
            unsigned b1 = *(const unsigned*)&sB[t * 8 + g][k0 + tg * 2 + 8];
            asm volatile(
                "mma.sync.aligned.m16n8k16.row.col.f32.bf16.bf16.f32 "
                "{%0,%1,%2,%3}, {%4,%5,%6,%7}, {%8,%9}, {%0,%1,%2,%3};"
                : "+f"(c[t][0]), "+f"(c[t][1]), "+f"(c[t][2]), "+f"(c[t][3])
                : "r"(a0), "r"(a1), "r"(a2), "r"(a3), "r"(b0), "r"(b1));
        }
    }

    int r0 = br + row0 + g;
    int r1 = r0 + 8;
#pragma unroll
    for (int t = 0; t < 16; t++) {
        int col = t * 8 + tg * 2;
        if (r0 < n) *(unsigned*)(g_t + (size_t)r0 * FDIM + col) = pack_bf2(c[t][0], c[t][1]);
        if (r1 < n) *(unsigned*)(g_t + (size_t)r1 * FDIM + col) = pack_bf2(c[t][2], c[t][3]);
    }
}

// fused gather + finalize. Half-warp per edge (16 lanes x 16B = 256B row),
// 4 edges per half-warp batch with next-batch CSR-entry prefetch.
__global__ __launch_bounds__(256) void k_gather(const float* __restrict__ b1, int n) {
    const int lane = threadIdx.x & 31;
    const int half = lane >> 4;
    const int hl   = lane & 15;
    const int wid  = threadIdx.x >> 5;
    const int gw   = blockIdx.x * 8 + wid;
    const int nw   = gridDim.x * 8;
    const uint4* trows = (const uint4*)g_t;   // 16 uint4 per row

    float b[8];
    {
        float4 b0 = __ldg((const float4*)b1 + hl * 2);
        float4 b1v = __ldg((const float4*)b1 + hl * 2 + 1);
        b[0] = b0.x; b[1] = b0.y; b[2] = b0.z; b[3] = b0.w;
        b[4] = b1v.x; b[5] = b1v.y; b[6] = b1v.z; b[7] = b1v.w;
    }
    float vacc[8];
#pragma unroll
    for (int k = 0; k < 8; k++) vacc[k] = 0.f;

    for (int i = gw; i < n; i += nw) {
        int end = __ldg(g_rowptr + i);        // post-fill cursor == row end
        int cnt = __ldg(g_cnt + i);
        int beg = end - cnt;
        float acc[8];
        {
            float di = __ldg(g_dinv + i);
            float selfw = half ? 0.f : di * di;
            float f[8];
            bf8_to_f8(__ldg(trows + ((size_t)i << 4) + hl), f);
#pragma unroll
            for (int k = 0; k < 8; k++) acc[k] = selfw * f[k];
        }
        int j = beg + half;
        if (j + 6 < end) {
            int2 e0 = __ldg(g_csr + j);
            int2 e1 = __ldg(g_csr + j + 2);
            int2 e2 = __ldg(g_csr + j + 4);
            int2 e3 = __ldg(g_csr + j + 6);
            while (true) {
                int jn = j + 8;
                bool more = (jn + 6 < end);
                int2 p0, p1, p2, p3;
                if (more) {
                    p0 = __ldg(g_csr + jn);
                    p1 = __ldg(g_csr + jn + 2);
                    p2 = __ldg(g_csr + jn + 4);
                    p3 = __ldg(g_csr + jn + 6);
                }
                uint4 u0 = __ldg(trows + ((size_t)e0.x << 4) + hl);
                uint4 u1 = __ldg(trows + ((size_t)e1.x << 4) + hl);
                uint4 u2 = __ldg(trows + ((size_t)e2.x << 4) + hl);
                uint4 u3 = __ldg(trows + ((size_t)e3.x << 4) + hl);
                float f0[8], f1[8], f2[8], f3[8];
                bf8_to_f8(u0, f0);
                bf8_to_f8(u1, f1);
                bf8_to_f8(u2, f2);
                bf8_to_f8(u3, f3);
                float n0 = __int_as_float(e0.y);
                float n1 = __int_as_float(e1.y);
                float n2 = __int_as_float(e2.y);
                float n3 = __int_as_float(e3.y);
#pragma unroll
                for (int k = 0; k < 8; k++) acc[k] = fmaf(n0, f0[k], acc[k]);
#pragma unroll
                for (int k = 0; k < 8; k++) acc[k] = fmaf(n1, f1[k], acc[k]);
#pragma unroll
                for (int k = 0; k < 8; k++) acc[k] = fmaf(n2, f2[k], acc[k]);
#pragma unroll
                for (int k = 0; k < 8; k++) acc[k] = fmaf(n3, f3[k], acc[k]);
                j = jn;
                if (!more) break;
                e0 = p0; e1 = p1; e2 = p2; e3 = p3;
            }
        }
        for (; j < end; j += 2) {
            int2 e0 = __ldg(g_csr + j);
            float f0[8];
            bf8_to_f8(__ldg(trows + ((size_t)e0.x << 4) + hl), f0);
            float n0 = __int_as_float(e0.y);
#pragma unroll
            for (int k = 0; k < 8; k++) acc[k] = fmaf(n0, f0[k], acc[k]);
        }
#pragma unroll
        for (int k = 0; k < 8; k++) acc[k] += __shfl_xor_sync(~0u, acc[k], 16);
        if (!half) {
            float ci = __ldg(g_c + i);
#pragma unroll
            for (int k = 0; k < 8; k++) {
                float h = fmaxf(acc[k] + b[k], 0.f);
                vacc[k] = fmaf(ci, h, vacc[k]);
            }
        }
    }

    __shared__ float sv[FDIM];
    if (threadIdx.x < FDIM) sv[threadIdx.x] = 0.f;
    __syncthreads();
    if (!half) {
#pragma unroll
        for (int k = 0; k < 8; k++) atomicAdd(&sv[hl * 8 + k], vacc[k]);
    }
    __syncthreads();
    if (threadIdx.x < 32) {
        float4 p = *(const float4*)&sv[threadIdx.x * 4];
        red_add_v4(g_v + threadIdx.x * 4, p);
    }
}

// head
__global__ void k_head(const float* __restrict__ W2, const float* __restrict__ b2,
                       const float* __restrict__ Wmu, const float* __restrict__ bmu,
                       const float* __restrict__ Wlv, const float* __restrict__ blv,
                       float* __restrict__ out, float invn) {
    __shared__ float vs[FDIM];
    __shared__ float gs[FDIM];
    int j = threadIdx.x;
    vs[j] = g_v[j];
    __syncthreads();
    float s = 0.f;
#pragma unroll 8
    for (int k = 0; k < FDIM; k++) s = fmaf(vs[k], W2[(size_t)k * FDIM + j], s);
    gs[j] = s * invn + b2[j];
    __syncthreads();
    if (j < LAT) {
        float m = bmu[j];
#pragma unroll 8
        for (int k = 0; k < FDIM; k++) m = fmaf(gs[k], Wmu[(size_t)k * LAT + j], m);
        out[j] = m;
    } else {
        int l = j - LAT;
        float m = blv[l];
#pragma unroll 8
        for (int k = 0; k < FDIM; k++) m = fmaf(gs[k], Wlv[(size_t)k * LAT + l], m);
        out[LAT + l] = m;
    }
}

// ---------------- launch -------------------------------------------------------
extern "C" void kernel_launch(void* const* d_in, const int* in_sizes, int n_in,
                              void* d_out, int out_size) {
    const float* x   = (const float*)d_in[0];
    const int*   ei  = (const int*)d_in[1];
    const float* w   = (const float*)d_in[2];
    const float* W1  = (const float*)d_in[3];
    const float* b1  = (const float*)d_in[4];
    const float* W2  = (const float*)d_in[5];
    const float* b2  = (const float*)d_in[6];
    const float* Wmu = (const float*)d_in[7];
    const float* bmu = (const float*)d_in[8];
    const float* Wlv = (const float*)d_in[9];
    const float* blv = (const float*)d_in[10];
    float* out = (float*)d_out;

    const int n = in_sizes[0] / FDIM;
    const int e = in_sizes[2];
    const int* src = ei;
    const int* dst = ei + e;
    const int nb_scan = (n + SCAN_ELEMS - 1) / SCAN_ELEMS;   // 391
    const int smem_gemm = 2 * 128 * SROW * (int)sizeof(__nv_bfloat16);  // 69,632 B

    static int s_attr_done = 0;
    if (!s_attr_done) {
        cudaFuncSetAttribute(k_gemm_tc, cudaFuncAttributeMaxDynamicSharedMemorySize, smem_gemm);
        s_attr_done = 1;
    }

    // Side stream for the independent GEMM (capture fork pattern, fork at t=0).
    cudaStream_t s2;
    cudaStreamCreate(&s2);
    cudaEvent_t ev_fork, ev_join;
    cudaEventCreateWithFlags(&ev_fork, cudaEventDisableTiming);
    cudaEventCreateWithFlags(&ev_join, cudaEventDisableTiming);

    cudaEventRecord(ev_fork, 0);
    cudaStreamWaitEvent(s2, ev_fork, 0);
    k_gemm_tc<<<(n + 127) / 128, 256, smem_gemm, s2>>>(x, W1, n);
    cudaEventRecord(ev_join, s2);

    // CSR-build chain (main stream), concurrent with GEMM.
    k_init<<<(n + 255) / 256, 256>>>(n);
    k_hist<<<(e + 255) / 256, 256>>>(dst, w, e);
    k_scan1<<<nb_scan, 256>>>(n);
    k_scan2<<<1, 512>>>(nb_scan);
    k_scan3<<<(n + 255) / 256, 256>>>(n);
    k_fill<<<(e + 255) / 256, 256>>>(src, dst, w, e);

    cudaStreamWaitEvent(0, ev_join, 0);
    k_gather<<<1184, 256>>>(b1, n);
    k_head<<<1, FDIM>>>(W2, b2, Wmu, bmu, Wlv, blv, out, 1.0f / (float)n);
}